// round 16
// baseline (speedup 1.0000x reference)
#include <cuda_runtime.h>
#include <math.h>
#include <stdint.h>

// Problem constants
#define LL      2
#define BATN    32
#define AN      64
#define BDOC    1024
#define DD      128
#define NBITS   1024
#define NW      (NBITS / 32)          // 32 words per code row
#define QROWS   (LL * BATN * AN)      // 4096
#define DROWS   (LL * BATN * BDOC)    // 65536

// Stage-1 GEMM tiling
#define BM  128     // rows per block
#define BNB 128     // bit-columns per block
#define BK  32      // k-chunk

// Scratch (no cudaMalloc allowed)
__device__ uint32_t g_qcodes[QROWS * NW];     // 512 KB
__device__ uint32_t g_dcodes[DROWS * NW];     // 8 MB
__device__ float    g_rT[DD * NBITS];         // 512 KB, [k][bit]

// ---------------------------------------------------------------------------
// Stage 0: transpose r [NBITS, D] -> g_rT [D, NBITS] (coalesced writes)
// ---------------------------------------------------------------------------
__global__ void transpose_r_kernel(const float* __restrict__ r) {
    int idx = blockIdx.x * 256 + threadIdx.x;   // over D*NBITS = 131072
    int k = idx >> 10;                          // idx / NBITS
    int c = idx & (NBITS - 1);
    g_rT[idx] = r[c * DD + k];
}

// ---------------------------------------------------------------------------
// Stage 1: fp32 sign-hash GEMM + bit packing.
// Block = 128 rows x 128 bit-cols, K=128 in 4 chunks of 32.
// 256 threads as 16x16 grid, 8x8 micro-tile each.
// ---------------------------------------------------------------------------
__global__ __launch_bounds__(256, 2) void codes_kernel(
    const float* __restrict__ qemb, const float* __restrict__ demb) {
    __shared__ float As[BM * BK];    // 16 KB, [row][k]
    __shared__ float Bs[BK * BNB];   // 16 KB, [k][col]

    const int tid = threadIdx.x;
    const int tc = tid & 15;         // col group
    const int tr = tid >> 4;         // row group

    const int rtile = blockIdx.x;
    const int c0 = blockIdx.y * BNB;

    const float* src;
    uint32_t* dst;
    int row0;
    if (rtile < QROWS / BM) {
        src = qemb; dst = g_qcodes; row0 = rtile * BM;
    } else {
        src = demb; dst = g_dcodes; row0 = (rtile - QROWS / BM) * BM;
    }

    float acc[8][8];
#pragma unroll
    for (int i = 0; i < 8; i++)
#pragma unroll
        for (int j = 0; j < 8; j++) acc[i][j] = 0.0f;

    const float2* As2 = (const float2*)As;
    const float4* Bs4 = (const float4*)Bs;

    for (int k0 = 0; k0 < DD; k0 += BK) {
        // Load A tile: 128 rows x 32 k = 1024 float4, 4 per thread (coalesced)
#pragma unroll
        for (int i = 0; i < 4; i++) {
            int idx = tid + i * 256;
            int rr = idx >> 3, k4 = idx & 7;
            ((float4*)As)[rr * (BK / 4) + k4] =
                *(const float4*)&src[(size_t)(row0 + rr) * DD + k0 + k4 * 4];
        }
        // Load B tile from rT: 32 k x 128 cols = 1024 float4 (coalesced, conflict-free store)
#pragma unroll
        for (int i = 0; i < 4; i++) {
            int idx = tid + i * 256;
            int kk = idx >> 5, c4 = idx & 31;
            ((float4*)Bs)[kk * (BNB / 4) + c4] =
                *(const float4*)&g_rT[(size_t)(k0 + kk) * NBITS + c0 + c4 * 4];
        }
        __syncthreads();

#pragma unroll 4
        for (int k = 0; k < BK; k += 2) {
            float4 b00 = Bs4[k * (BNB / 4) + tc * 2];
            float4 b01 = Bs4[k * (BNB / 4) + tc * 2 + 1];
            float4 b10 = Bs4[(k + 1) * (BNB / 4) + tc * 2];
            float4 b11 = Bs4[(k + 1) * (BNB / 4) + tc * 2 + 1];
#pragma unroll
            for (int i = 0; i < 8; i++) {
                float2 a = As2[(tr * 8 + i) * (BK / 2) + (k >> 1)];
                acc[i][0] += a.x * b00.x; acc[i][1] += a.x * b00.y;
                acc[i][2] += a.x * b00.z; acc[i][3] += a.x * b00.w;
                acc[i][4] += a.x * b01.x; acc[i][5] += a.x * b01.y;
                acc[i][6] += a.x * b01.z; acc[i][7] += a.x * b01.w;
                acc[i][0] += a.y * b10.x; acc[i][1] += a.y * b10.y;
                acc[i][2] += a.y * b10.z; acc[i][3] += a.y * b10.w;
                acc[i][4] += a.y * b11.x; acc[i][5] += a.y * b11.y;
                acc[i][6] += a.y * b11.z; acc[i][7] += a.y * b11.w;
            }
        }
        __syncthreads();
    }

    // Epilogue: sign bits -> smem bytes (reuse As: exactly 128*128 = 16384 B)
    unsigned char* sb = (unsigned char*)As;
#pragma unroll
    for (int i = 0; i < 8; i++)
#pragma unroll
        for (int j = 0; j < 8; j++)
            sb[(tr * 8 + i) * BNB + tc * 8 + j] = (acc[i][j] > 0.0f) ? 1 : 0;
    __syncthreads();

    // Pack 512 words (128 rows x 4 words), 2 per thread
    for (int w = tid; w < BM * 4; w += 256) {
        int row = w >> 2, wc = w & 3;
        const uint32_t* sw = (const uint32_t*)(sb + row * BNB + wc * 32);
        uint32_t bits = 0;
#pragma unroll
        for (int q8 = 0; q8 < 8; q8++) {
            uint32_t v = sw[q8];
            bits |= (v & 1u) << (q8 * 4);
            bits |= ((v >> 8) & 1u) << (q8 * 4 + 1);
            bits |= ((v >> 16) & 1u) << (q8 * 4 + 2);
            bits |= ((v >> 24) & 1u) << (q8 * 4 + 3);
        }
        dst[(size_t)(row0 + row) * NW + blockIdx.y * 4 + wc] = bits;
    }
}

// ---------------------------------------------------------------------------
// Stage 2: ham = popc(q ^ d), sim = cos(pi/NBITS * ham), mask, transposed write.
// Block = one (l, bat) x 256 doc cols. Query codes (8 KB) in smem.
// ---------------------------------------------------------------------------
__global__ __launch_bounds__(256) void simmat_kernel(
    const int* __restrict__ qtok, const int* __restrict__ dtok,
    float* __restrict__ out) {
    __shared__ uint32_t qs[AN][NW];        // 8 KB
    __shared__ unsigned char qm[AN];

    const int lb = blockIdx.y;             // 0..63
    const int l = lb >> 5;                 // / BATN
    const int bat = lb & 31;
    const int tid = threadIdx.x;
    const int c = blockIdx.x * 256 + tid;  // doc col 0..1023
    const int base = l * BATN + bat;

    for (int idx = tid; idx < AN * NW; idx += 256)
        ((uint32_t*)qs)[idx] = g_qcodes[(size_t)base * AN * NW + idx];
    if (tid < AN) qm[tid] = (qtok[bat * AN + tid] == 0) ? 1 : 0;
    __syncthreads();

    // Doc code row into registers (vectorized)
    uint32_t dreg[NW];
    const uint4* dp4 = (const uint4*)&g_dcodes[((size_t)base * BDOC + c) * NW];
#pragma unroll
    for (int w4 = 0; w4 < NW / 4; w4++) {
        uint4 v = dp4[w4];
        dreg[w4 * 4 + 0] = v.x; dreg[w4 * 4 + 1] = v.y;
        dreg[w4 * 4 + 2] = v.z; dreg[w4 * 4 + 3] = v.w;
    }
    const bool dm = (dtok[bat * BDOC + c] == 0);
    const float pf = (float)(M_PI / (double)NBITS);

    float* op = out + ((size_t)(bat * LL + l) * AN) * BDOC + c;

    for (int a0 = 0; a0 < AN; a0 += 16) {
        int ham[16];
#pragma unroll
        for (int i = 0; i < 16; i++) ham[i] = 0;
#pragma unroll 8
        for (int w = 0; w < NW; w++) {
            uint32_t dv = dreg[w];
#pragma unroll
            for (int i = 0; i < 16; i++)
                ham[i] += __popc(qs[a0 + i][w] ^ dv);   // smem broadcast read
        }
#pragma unroll
        for (int i = 0; i < 16; i++) {
            int a = a0 + i;
            float sim = (dm || qm[a]) ? 0.0f : cosf(pf * (float)ham[i]);
            op[(size_t)a * BDOC] = sim;
        }
    }
}

// ---------------------------------------------------------------------------
extern "C" void kernel_launch(void* const* d_in, const int* in_sizes, int n_in,
                              void* d_out, int out_size) {
    const float* qemb = (const float*)d_in[0];   // [L,BAT,A,D]
    const float* demb = (const float*)d_in[1];   // [L,BAT,B,D]
    const int*   qtok = (const int*)d_in[2];     // [BAT,A]
    const int*   dtok = (const int*)d_in[3];     // [BAT,B]
    const float* r    = (const float*)d_in[4];   // [NBITS,D]
    float* out = (float*)d_out;                  // [BAT,L,A,B]

    transpose_r_kernel<<<(DD * NBITS) / 256, 256>>>(r);
    codes_kernel<<<dim3(QROWS / BM + DROWS / BM, NBITS / BNB), 256>>>(qemb, demb);
    simmat_kernel<<<dim3(BDOC / 256, LL * BATN), 256>>>(qtok, dtok, out);
}

// round 17
// speedup vs baseline: 1.0326x; 1.0326x over previous
#include <cuda_runtime.h>
#include <math.h>
#include <stdint.h>

// Problem constants
#define LL      2
#define BATN    32
#define AN      64
#define BDOC    1024
#define DD      128
#define NBITS   1024
#define NW      (NBITS / 32)          // 32 words per code row
#define QROWS   (LL * BATN * AN)      // 4096
#define DROWS   (LL * BATN * BDOC)    // 65536

// Stage-1 GEMM tiling
#define BM  128     // rows per block
#define BNB 128     // bit-columns per block
#define BK  32      // k-chunk

// Scratch (no cudaMalloc allowed)
__device__ uint32_t g_qcodes[QROWS * NW];     // 512 KB
__device__ uint32_t g_dcodes[DROWS * NW];     // 8 MB
__device__ float    g_rT[DD * NBITS];         // 512 KB, [k][bit]

// ---------------------------------------------------------------------------
// f32x2 packed-FMA helpers (sm_103a paired fp32 datapath; bit-identical per
// lane to scalar FFMA, so sign decisions are unchanged vs the fp32 baseline)
// ---------------------------------------------------------------------------
__device__ __forceinline__ unsigned long long pk2(float lo, float hi) {
    unsigned long long r;
    asm("mov.b64 %0, {%1, %2};" : "=l"(r) : "f"(lo), "f"(hi));
    return r;
}
__device__ __forceinline__ void fma2(unsigned long long& d,
                                     unsigned long long a,
                                     unsigned long long b) {
    asm("fma.rn.f32x2 %0, %1, %2, %0;" : "+l"(d) : "l"(a), "l"(b));
}
__device__ __forceinline__ void upk2(unsigned long long v, float& lo, float& hi) {
    asm("mov.b64 {%0, %1}, %2;" : "=f"(lo), "=f"(hi) : "l"(v));
}

// ---------------------------------------------------------------------------
// Stage 0: transpose r [NBITS, D] -> g_rT [D, NBITS] (coalesced writes)
// ---------------------------------------------------------------------------
__global__ void transpose_r_kernel(const float* __restrict__ r) {
    int idx = blockIdx.x * 256 + threadIdx.x;   // over D*NBITS = 131072
    int k = idx >> 10;                          // idx / NBITS
    int c = idx & (NBITS - 1);
    g_rT[idx] = r[c * DD + k];
}

// ---------------------------------------------------------------------------
// Stage 1: fp32 sign-hash GEMM + bit packing, mainloop on fma.rn.f32x2.
// Block = 128 rows x 128 bit-cols, K=128 in 4 chunks of 32.
// 256 threads as 16x16 grid, 8x8 micro-tile each; acc packed pairwise in j.
// ---------------------------------------------------------------------------
__global__ __launch_bounds__(256, 2) void codes_kernel(
    const float* __restrict__ qemb, const float* __restrict__ demb) {
    __shared__ float As[BM * BK];    // 16 KB, [row][k]
    __shared__ float Bs[BK * BNB];   // 16 KB, [k][col]

    const int tid = threadIdx.x;
    const int tc = tid & 15;         // col group
    const int tr = tid >> 4;         // row group

    const int rtile = blockIdx.x;
    const int c0 = blockIdx.y * BNB;

    const float* src;
    uint32_t* dst;
    int row0;
    if (rtile < QROWS / BM) {
        src = qemb; dst = g_qcodes; row0 = rtile * BM;
    } else {
        src = demb; dst = g_dcodes; row0 = (rtile - QROWS / BM) * BM;
    }

    // acc2[i][j2] = packed pair (acc[i][2*j2], acc[i][2*j2+1])
    unsigned long long acc2[8][4];
#pragma unroll
    for (int i = 0; i < 8; i++)
#pragma unroll
        for (int j = 0; j < 4; j++) acc2[i][j] = 0ull;

    const float2* As2 = (const float2*)As;

    for (int k0 = 0; k0 < DD; k0 += BK) {
        // Load A tile: 128 rows x 32 k = 1024 float4, 4 per thread (coalesced)
#pragma unroll
        for (int i = 0; i < 4; i++) {
            int idx = tid + i * 256;
            int rr = idx >> 3, k4 = idx & 7;
            ((float4*)As)[rr * (BK / 4) + k4] =
                *(const float4*)&src[(size_t)(row0 + rr) * DD + k0 + k4 * 4];
        }
        // Load B tile from rT: 32 k x 128 cols = 1024 float4 (coalesced)
#pragma unroll
        for (int i = 0; i < 4; i++) {
            int idx = tid + i * 256;
            int kk = idx >> 5, c4 = idx & 31;
            ((float4*)Bs)[kk * (BNB / 4) + c4] =
                *(const float4*)&g_rT[(size_t)(k0 + kk) * NBITS + c0 + c4 * 4];
        }
        __syncthreads();

#pragma unroll 4
        for (int k = 0; k < BK; k += 2) {
            // b row pairs: 8 floats = 4 b64 pairs per k-row (16B-aligned LDS.128)
            ulonglong2 bk0a = *(const ulonglong2*)&Bs[k * BNB + tc * 8];
            ulonglong2 bk0b = *(const ulonglong2*)&Bs[k * BNB + tc * 8 + 4];
            ulonglong2 bk1a = *(const ulonglong2*)&Bs[(k + 1) * BNB + tc * 8];
            ulonglong2 bk1b = *(const ulonglong2*)&Bs[(k + 1) * BNB + tc * 8 + 4];
#pragma unroll
            for (int i = 0; i < 8; i++) {
                float2 a = As2[(tr * 8 + i) * (BK / 2) + (k >> 1)];
                unsigned long long ax = pk2(a.x, a.x);   // broadcast pack (alu pipe)
                unsigned long long ay = pk2(a.y, a.y);
                fma2(acc2[i][0], ax, bk0a.x);
                fma2(acc2[i][1], ax, bk0a.y);
                fma2(acc2[i][2], ax, bk0b.x);
                fma2(acc2[i][3], ax, bk0b.y);
                fma2(acc2[i][0], ay, bk1a.x);
                fma2(acc2[i][1], ay, bk1a.y);
                fma2(acc2[i][2], ay, bk1b.x);
                fma2(acc2[i][3], ay, bk1b.y);
            }
        }
        __syncthreads();
    }

    // Epilogue: sign bits -> smem bytes (reuse As: exactly 128*128 = 16384 B)
    unsigned char* sb = (unsigned char*)As;
#pragma unroll
    for (int i = 0; i < 8; i++)
#pragma unroll
        for (int j2 = 0; j2 < 4; j2++) {
            float lo, hi;
            upk2(acc2[i][j2], lo, hi);
            sb[(tr * 8 + i) * BNB + tc * 8 + j2 * 2]     = (lo > 0.0f) ? 1 : 0;
            sb[(tr * 8 + i) * BNB + tc * 8 + j2 * 2 + 1] = (hi > 0.0f) ? 1 : 0;
        }
    __syncthreads();

    // Pack 512 words (128 rows x 4 words), 2 per thread
    for (int w = tid; w < BM * 4; w += 256) {
        int row = w >> 2, wc = w & 3;
        const uint32_t* sw = (const uint32_t*)(sb + row * BNB + wc * 32);
        uint32_t bits = 0;
#pragma unroll
        for (int q8 = 0; q8 < 8; q8++) {
            uint32_t v = sw[q8];
            bits |= (v & 1u) << (q8 * 4);
            bits |= ((v >> 8) & 1u) << (q8 * 4 + 1);
            bits |= ((v >> 16) & 1u) << (q8 * 4 + 2);
            bits |= ((v >> 24) & 1u) << (q8 * 4 + 3);
        }
        dst[(size_t)(row0 + row) * NW + blockIdx.y * 4 + wc] = bits;
    }
}

// ---------------------------------------------------------------------------
// Stage 2: ham = popc(q ^ d), sim = cos(pi/NBITS * ham), mask, transposed write.
// Block = one (l, bat) x 256 doc cols. Query codes (8 KB) in smem.
// ---------------------------------------------------------------------------
__global__ __launch_bounds__(256) void simmat_kernel(
    const int* __restrict__ qtok, const int* __restrict__ dtok,
    float* __restrict__ out) {
    __shared__ uint32_t qs[AN][NW];        // 8 KB
    __shared__ unsigned char qm[AN];

    const int lb = blockIdx.y;             // 0..63
    const int l = lb >> 5;                 // / BATN
    const int bat = lb & 31;
    const int tid = threadIdx.x;
    const int c = blockIdx.x * 256 + tid;  // doc col 0..1023
    const int base = l * BATN + bat;

    for (int idx = tid; idx < AN * NW; idx += 256)
        ((uint32_t*)qs)[idx] = g_qcodes[(size_t)base * AN * NW + idx];
    if (tid < AN) qm[tid] = (qtok[bat * AN + tid] == 0) ? 1 : 0;
    __syncthreads();

    // Doc code row into registers (vectorized)
    uint32_t dreg[NW];
    const uint4* dp4 = (const uint4*)&g_dcodes[((size_t)base * BDOC + c) * NW];
#pragma unroll
    for (int w4 = 0; w4 < NW / 4; w4++) {
        uint4 v = dp4[w4];
        dreg[w4 * 4 + 0] = v.x; dreg[w4 * 4 + 1] = v.y;
        dreg[w4 * 4 + 2] = v.z; dreg[w4 * 4 + 3] = v.w;
    }
    const bool dm = (dtok[bat * BDOC + c] == 0);
    const float pf = (float)(M_PI / (double)NBITS);

    float* op = out + ((size_t)(bat * LL + l) * AN) * BDOC + c;

    for (int a0 = 0; a0 < AN; a0 += 16) {
        int ham[16];
#pragma unroll
        for (int i = 0; i < 16; i++) ham[i] = 0;
#pragma unroll 8
        for (int w = 0; w < NW; w++) {
            uint32_t dv = dreg[w];
#pragma unroll
            for (int i = 0; i < 16; i++)
                ham[i] += __popc(qs[a0 + i][w] ^ dv);   // smem broadcast read
        }
#pragma unroll
        for (int i = 0; i < 16; i++) {
            int a = a0 + i;
            float sim = (dm || qm[a]) ? 0.0f : cosf(pf * (float)ham[i]);
            op[(size_t)a * BDOC] = sim;
        }
    }
}

// ---------------------------------------------------------------------------
extern "C" void kernel_launch(void* const* d_in, const int* in_sizes, int n_in,
                              void* d_out, int out_size) {
    const float* qemb = (const float*)d_in[0];   // [L,BAT,A,D]
    const float* demb = (const float*)d_in[1];   // [L,BAT,B,D]
    const int*   qtok = (const int*)d_in[2];     // [BAT,A]
    const int*   dtok = (const int*)d_in[3];     // [BAT,B]
    const float* r    = (const float*)d_in[4];   // [NBITS,D]
    float* out = (float*)d_out;                  // [BAT,L,A,B]

    transpose_r_kernel<<<(DD * NBITS) / 256, 256>>>(r);
    codes_kernel<<<dim3(QROWS / BM + DROWS / BM, NBITS / BNB), 256>>>(qemb, demb);
    simmat_kernel<<<dim3(BDOC / 256, LL * BATN), 256>>>(qtok, dtok, out);
}